// round 13
// baseline (speedup 1.0000x reference)
#include <cuda_runtime.h>
#include <cuda_fp16.h>
#include <math.h>
#include <stdint.h>

#define Bn 65536
#define K1 1664
#define Nn 200000

// ---------- scratch ----------
__device__ __align__(128) __half hX1a[(size_t)Bn * K1];
__device__ __align__(128) __half hMem[(size_t)2 * Bn * 512];   // [src_mem; dst_mem]
__device__ __align__(128) __half hH1[(size_t)2 * Bn * 512];    // [H1a; H1b]
__device__ __align__(128) __half hM[(size_t)2 * Bn * 512];     // [Ms; Md]
__device__ __align__(128) __half hGh[(size_t)2 * Bn * 1536];   // [gh_s; gh_d] (fp16)
__device__ __align__(128) __half hGi[(size_t)2 * Bn * 1536];   // [gi_d; gi_s]
__device__ __align__(128) __half hC[(size_t)2 * Bn * 1024];    // [Cs; Cd]
__device__ __align__(128) __half hW1s[1024 * K1];              // [W1; W1perm]
__device__ __align__(128) __half hW2[512 * 512];
__device__ __align__(128) __half hWih[1536 * 512];
__device__ __align__(128) __half hWhh[1536 * 512];
__device__ __align__(128) __half hWo[512 * 1024];
__device__ float dB1[1024];

// ---------- asm ----------
__device__ __forceinline__ uint32_t smem_u32(const void* p) {
    uint32_t a;
    asm("{ .reg .u64 t; cvta.to.shared.u64 t, %1; cvt.u32.u64 %0, t; }" : "=r"(a) : "l"(p));
    return a;
}
__device__ __forceinline__ void cp16(uint32_t d, const void* s) {
    asm volatile("cp.async.cg.shared.global [%0], [%1], 16;" :: "r"(d), "l"(s) : "memory");
}
#define CP_COMMIT() asm volatile("cp.async.commit_group;" ::: "memory")
#define CP_WAIT1() asm volatile("cp.async.wait_group 1;" ::: "memory")
#define LDSM4(r, a) \
    asm volatile("ldmatrix.sync.aligned.m8n8.x4.shared.b16 {%0,%1,%2,%3},[%4];" \
        : "=r"((r)[0]), "=r"((r)[1]), "=r"((r)[2]), "=r"((r)[3]) : "r"(a))
#define LDSM4B(r0, r1, a) \
    asm volatile("ldmatrix.sync.aligned.m8n8.x4.shared.b16 {%0,%1,%2,%3},[%4];" \
        : "=r"((r0)[0]), "=r"((r0)[1]), "=r"((r1)[0]), "=r"((r1)[1]) : "r"(a))
#define MMAH(d, a, b) \
    asm volatile("mma.sync.aligned.m16n8k16.row.col.f32.f16.f16.f32 " \
        "{%0,%1,%2,%3},{%4,%5,%6,%7},{%8,%9},{%0,%1,%2,%3};" \
        : "+f"((d)[0]), "+f"((d)[1]), "+f"((d)[2]), "+f"((d)[3]) \
        : "r"((a)[0]), "r"((a)[1]), "r"((a)[2]), "r"((a)[3]), "r"((b)[0]), "r"((b)[1]))

// ---------- fp16 GEMM: C = A @ B^T + bias ----------
// Block 128x128, BK=64 (128B rows), 4 warps (64x64 warp tile), 3-stage
// cp.async, XOR swizzle (chunk c of row r at r*128 + 16*(c^(r&7))),
// manual fragment double-buffering across the 4 ks-steps.
// mode 0: fp32 C; 1: relu->half; 2: ->half; 3: relu->half row-split dual out.
#define A_B 16384
#define STG (2 * A_B)
#define GSMEM (3 * STG)

__global__ void __launch_bounds__(128, 2)
hgemm(const __half* __restrict__ A, int lda,
      const __half* __restrict__ B, int ldb, int K,
      const float* __restrict__ bias,
      float* __restrict__ C, int ldc,
      __half* __restrict__ H, int ldo, int mode)
{
    extern __shared__ __align__(128) char smx[];
    const uint32_t sbase = smem_u32(smx);
    const int tid = threadIdx.x, wid = tid >> 5, lane = tid & 31;
    const int wr = wid >> 1, wc = wid & 1;
    const size_t rowA = (size_t)blockIdx.y * 128;
    const int colB = blockIdx.x * 128;
    const __half* pA = A + (rowA + tid) * lda;
    const __half* pB = B + ((size_t)colB + tid) * ldb;
    const int key = tid & 7;

    float acc[4][8][4];
#pragma unroll
    for (int i = 0; i < 4; i++)
#pragma unroll
        for (int j = 0; j < 8; j++) {
            acc[i][j][0] = 0.f; acc[i][j][1] = 0.f;
            acc[i][j][2] = 0.f; acc[i][j][3] = 0.f;
        }

    const int nk = K >> 6;
    auto load_stage = [&](int kt, int s) {
        const int kc = kt << 6;
        uint32_t dA = sbase + s * STG + tid * 128;
#pragma unroll
        for (int c = 0; c < 8; c++) {
            cp16(dA + 16 * (c ^ key), pA + kc + c * 8);
            cp16(dA + A_B + 16 * (c ^ key), pB + kc + c * 8);
        }
        CP_COMMIT();
    };
    load_stage(0, 0);
    load_stage(1, 1);

    const int g = lane >> 3, r8 = lane & 7;
    const uint32_t aRowOff = (uint32_t)((wr * 64 + (g & 1) * 8 + r8) * 128);
    const uint32_t bRowOff = (uint32_t)((wc * 64 + (g >> 1) * 8 + r8) * 128) + A_B;
    const int aCk = g >> 1, bCk = g & 1;

    uint32_t st = 0;
    uint32_t av[2][4][4], bv[2][8][2];
    auto ldfr = [&](int ks, int buf) {
        const uint32_t ach = (uint32_t)(16 * ((2 * ks + aCk) ^ r8));
        const uint32_t bch = (uint32_t)(16 * ((2 * ks + bCk) ^ r8));
#pragma unroll
        for (int mt = 0; mt < 4; mt++)
            LDSM4(av[buf][mt], st + aRowOff + (uint32_t)(mt * 2048) + ach);
#pragma unroll
        for (int np = 0; np < 4; np++)
            LDSM4B(bv[buf][2 * np], bv[buf][2 * np + 1],
                   st + bRowOff + (uint32_t)(np * 2048) + bch);
    };

    int s_cur = 0, s_nxt = 2;
    for (int kt = 0; kt < nk; ++kt) {
        CP_WAIT1();
        __syncthreads();
        st = sbase + s_cur * STG;
        ldfr(0, 0);
        if (kt + 2 < nk) load_stage(kt + 2, s_nxt);
        else CP_COMMIT();
#pragma unroll
        for (int ks = 0; ks < 4; ks++) {
            if (ks < 3) ldfr(ks + 1, (ks + 1) & 1);
            const int b = ks & 1;
#pragma unroll
            for (int mt = 0; mt < 4; mt++)
#pragma unroll
                for (int nt = 0; nt < 8; nt++)
                    MMAH(acc[mt][nt], av[b][mt], bv[b][nt]);
        }
        if (++s_cur == 3) s_cur = 0;
        if (++s_nxt == 3) s_nxt = 0;
    }

    __half* Hb = H;
    int cSub = 0;
    if (mode == 3 && colB >= 512) { Hb = H + (size_t)Bn * 512; cSub = 512; }
    const int doRelu = (mode == 1 || mode == 3);

#pragma unroll
    for (int mt = 0; mt < 4; mt++) {
        size_t r0 = rowA + wr * 64 + mt * 16 + (lane >> 2);
#pragma unroll
        for (int nt = 0; nt < 8; nt++) {
            int col = colB + wc * 64 + nt * 8 + (lane & 3) * 2;
            float b0 = bias[col], b1 = bias[col + 1];
            float v0 = acc[mt][nt][0] + b0, v1 = acc[mt][nt][1] + b1;
            float v2 = acc[mt][nt][2] + b0, v3 = acc[mt][nt][3] + b1;
            if (mode == 0) {
                *(float2*)(C + r0 * ldc + col) = make_float2(v0, v1);
                *(float2*)(C + (r0 + 8) * ldc + col) = make_float2(v2, v3);
            } else {
                if (doRelu) {
                    v0 = fmaxf(v0, 0.f); v1 = fmaxf(v1, 0.f);
                    v2 = fmaxf(v2, 0.f); v3 = fmaxf(v3, 0.f);
                }
                int cs = col - cSub;
                *(__half2*)(Hb + r0 * ldo + cs) = __floats2half2_rn(v0, v1);
                *(__half2*)(Hb + (r0 + 8) * ldo + cs) = __floats2half2_rn(v2, v3);
            }
        }
    }
}

// ---------- elementwise ----------
__global__ void conv_h(const float* __restrict__ w, __half* __restrict__ h, int n) {
    int i = blockIdx.x * blockDim.x + threadIdx.x;
    if (i < n / 2) {
        float2 v = *(const float2*)(w + 2 * i);
        *(__half2*)(h + 2 * i) = __floats2half2_rn(v.x, v.y);
    }
}

__global__ void w1_pack(const float* __restrict__ w1) {
    int i = blockIdx.x * blockDim.x + threadIdx.x;
    if (i >= 1024 * K1) return;
    int n = i / K1, k = i % K1;
    int src;
    if (n < 512) src = n * K1 + k;
    else {
        int kk = (k < 512) ? k + 512 : (k < 1024 ? k - 512 : k);
        src = (n - 512) * K1 + kk;
    }
    hW1s[i] = __float2half(w1[src]);
}

__global__ void b1_pack(const float* __restrict__ b) {
    int i = threadIdx.x + blockIdx.x * blockDim.x;
    if (i < 1024) dB1[i] = b[i & 511];
}

__global__ void gather_pack(const float* __restrict__ mem, const float* __restrict__ edge,
                            const float* __restrict__ ts, const float* __restrict__ tw,
                            const float* __restrict__ tb,
                            const int* __restrict__ sid, const int* __restrict__ did) {
    int row = blockIdx.x, t = threadIdx.x;   // 256
    size_t ra = (size_t)row * K1;
    int si = sid[row], di = did[row];
    float2 s2 = *(const float2*)(mem + (size_t)si * 512 + 2 * t);
    float2 d2 = *(const float2*)(mem + (size_t)di * 512 + 2 * t);
    float2 e2 = *(const float2*)(edge + (size_t)row * 512 + 2 * t);
    __half2 hs = __floats2half2_rn(s2.x, s2.y);
    __half2 hd = __floats2half2_rn(d2.x, d2.y);
    __half2 he = __floats2half2_rn(e2.x, e2.y);
    *(__half2*)(hX1a + ra + 2 * t) = hs;
    *(__half2*)(hX1a + ra + 512 + 2 * t) = hd;
    *(__half2*)(hX1a + ra + 1024 + 2 * t) = he;
    *(__half2*)(hMem + (size_t)row * 512 + 2 * t) = hs;
    *(__half2*)(hMem + (size_t)(Bn + row) * 512 + 2 * t) = hd;
    if (t < 64) {
        float tt = ts[row];
        float cx = cosf(tt * tw[2 * t] + tb[2 * t]);
        float cy = cosf(tt * tw[2 * t + 1] + tb[2 * t + 1]);
        *(__half2*)(hX1a + ra + 1536 + 2 * t) = __floats2half2_rn(cx, cy);
    }
}

__global__ void emb_pack(const float* __restrict__ se, const float* __restrict__ de) {
    int row = blockIdx.x, t = threadIdx.x;  // 256
    float2 a = *(const float2*)(se + (size_t)row * 512 + 2 * t);
    float2 b = *(const float2*)(de + (size_t)row * 512 + 2 * t);
    *(__half2*)(hC + (size_t)row * 1024 + 512 + 2 * t) = __floats2half2_rn(a.x, a.y);
    *(__half2*)(hC + (size_t)(Bn + row) * 1024 + 512 + 2 * t) = __floats2half2_rn(b.x, b.y);
}

__device__ __forceinline__ float sigf(float x) { return 1.0f / (1.0f + expf(-x)); }
__device__ __forceinline__ float4 ld4h(const __half* p) {
    __half2 a = *(const __half2*)p, b = *(const __half2*)(p + 2);
    float2 fa = __half22float2(a), fb = __half22float2(b);
    return make_float4(fa.x, fa.y, fb.x, fb.y);
}

__global__ void gru_scatter(const __half* __restrict__ gi, const __half* __restrict__ gh,
                            const float* __restrict__ mem, const int* __restrict__ ids,
                            __half* __restrict__ ch, float* __restrict__ out_mem) {
    int row = blockIdx.x, j = threadIdx.x * 4, id = ids[row];
    size_t b3 = (size_t)row * 1536;
    float4 ir = ld4h(gi + b3 + j);
    float4 hr = ld4h(gh + b3 + j);
    float4 iz = ld4h(gi + b3 + 512 + j);
    float4 hz = ld4h(gh + b3 + 512 + j);
    float4 in4 = ld4h(gi + b3 + 1024 + j);
    float4 hn = ld4h(gh + b3 + 1024 + j);
    float4 hv = *(const float4*)(mem + (size_t)id * 512 + j);
    float4 u;
    { float r = sigf(ir.x + hr.x), z = sigf(iz.x + hz.x);
      float n = tanhf(in4.x + r * hn.x); u.x = (1.f - z) * n + z * hv.x; }
    { float r = sigf(ir.y + hr.y), z = sigf(iz.y + hz.y);
      float n = tanhf(in4.y + r * hn.y); u.y = (1.f - z) * n + z * hv.y; }
    { float r = sigf(ir.z + hr.z), z = sigf(iz.z + hz.z);
      float n = tanhf(in4.z + r * hn.z); u.z = (1.f - z) * n + z * hv.z; }
    { float r = sigf(ir.w + hr.w), z = sigf(iz.w + hz.w);
      float n = tanhf(in4.w + r * hn.w); u.w = (1.f - z) * n + z * hv.w; }
    *(float4*)(out_mem + (size_t)id * 512 + j) = u;
    size_t cb = (size_t)row * 1024 + j;
    *(__half2*)(ch + cb) = __floats2half2_rn(u.x, u.y);
    *(__half2*)(ch + cb + 2) = __floats2half2_rn(u.z, u.w);
}

// ---------- launch ----------
extern "C" void kernel_launch(void* const* d_in, const int* in_sizes, int n_in,
                              void* d_out, int out_size) {
    const float* src_emb  = (const float*)d_in[0];
    const float* dst_emb  = (const float*)d_in[1];
    const float* edge     = (const float*)d_in[2];
    const float* ts       = (const float*)d_in[3];
    const float* memory   = (const float*)d_in[4];
    const float* time_w   = (const float*)d_in[5];
    const float* time_b   = (const float*)d_in[6];
    const float* msg_w1   = (const float*)d_in[7];
    const float* msg_b1   = (const float*)d_in[8];
    const float* msg_w2   = (const float*)d_in[9];
    const float* msg_b2   = (const float*)d_in[10];
    const float* gru_w_ih = (const float*)d_in[11];
    const float* gru_w_hh = (const float*)d_in[12];
    const float* gru_b_ih = (const float*)d_in[13];
    const float* gru_b_hh = (const float*)d_in[14];
    const float* out_w    = (const float*)d_in[15];
    const float* out_b    = (const float*)d_in[16];
    const int*   src_ids  = (const int*)d_in[17];
    const int*   dst_ids  = (const int*)d_in[18];

    float* out_y = (float*)d_out;
    float* out_mem = out_y + (size_t)2 * Bn * 512;

    cudaFuncSetAttribute(hgemm, cudaFuncAttributeMaxDynamicSharedMemorySize, GSMEM);

#define SH(p, g) __half* p; cudaGetSymbolAddress((void**)&p, g)
#define SF(p, g) float* p; cudaGetSymbolAddress((void**)&p, g)
    SH(pXa, hX1a); SH(pMem, hMem); SH(pH1, hH1); SH(pM, hM); SH(pC, hC);
    SH(pGh, hGh); SH(pGi, hGi);
    SH(pW1s, hW1s); SH(pW2, hW2); SH(pWih, hWih); SH(pWhh, hWhh); SH(pWo, hWo);
    SF(pB1, dB1);
#undef SH
#undef SF

    cudaMemcpyAsync(out_mem, memory, (size_t)Nn * 512 * sizeof(float),
                    cudaMemcpyDeviceToDevice, 0);

    #define CVT(src, dst, n) conv_h<<<((n) / 2 + 255) / 256, 256>>>(src, dst, n)

    w1_pack<<<(1024 * K1 + 255) / 256, 256>>>(msg_w1);
    b1_pack<<<4, 256>>>(msg_b1);
    gather_pack<<<Bn, 256>>>(memory, edge, ts, time_w, time_b, src_ids, dst_ids);
    CVT(gru_w_hh, pWhh, 1536 * 512);

    // layer1 fused: [H1a|H1b] <- X1a @ [W1;W1p]^T, relu, row-split output
    hgemm<<<dim3(8, Bn / 128), 128, GSMEM>>>(pXa, K1, pW1s, K1, K1, pB1,
                                             (float*)0, 0, pH1, 512, 3);
    // gh: [gh_s; gh_d] <- [src_mem; dst_mem] @ Whh^T (fp16 out)
    hgemm<<<dim3(12, 2 * Bn / 128), 128, GSMEM>>>(pMem, 512, pWhh, 512, 512,
                                                  gru_b_hh, (float*)0, 0, pGh, 1536, 2);
    CVT(msg_w2, pW2, 512 * 512);
    // msg2: [Ms; Md] <- [H1a; H1b] @ W2^T
    hgemm<<<dim3(4, 2 * Bn / 128), 128, GSMEM>>>(pH1, 512, pW2, 512, 512,
                                                 msg_b2, (float*)0, 0, pM, 512, 2);
    CVT(gru_w_ih, pWih, 1536 * 512);
    // gi: rows 0:Bn = Ms@Wih (gi_dst), Bn:2Bn = Md@Wih (gi_src) (fp16 out)
    hgemm<<<dim3(12, 2 * Bn / 128), 128, GSMEM>>>(pM, 512, pWih, 512, 512,
                                                  gru_b_ih, (float*)0, 0, pGi, 1536, 2);
    emb_pack<<<Bn, 256>>>(src_emb, dst_emb);
    gru_scatter<<<Bn, 128>>>(pGi + (size_t)Bn * 1536, pGh, memory, src_ids,
                             pC, out_mem);
    gru_scatter<<<Bn, 128>>>(pGi, pGh + (size_t)Bn * 1536, memory, dst_ids,
                             pC + (size_t)Bn * 1024, out_mem);
    CVT(out_w, pWo, 512 * 1024);
    // output projection: [2Bn,512] directly into d_out
    hgemm<<<dim3(4, 2 * Bn / 128), 128, GSMEM>>>(pC, 1024, pWo, 1024, 1024,
                                                 out_b, out_y, 512, (__half*)0, 0, 0);
}

// round 15
// speedup vs baseline: 1.1455x; 1.1455x over previous
#include <cuda_runtime.h>
#include <cuda_fp16.h>
#include <math.h>
#include <stdint.h>

#define Bn 65536
#define K1 1664
#define Nn 200000

// ---------- scratch ----------
__device__ __align__(128) __half hX1a[(size_t)Bn * K1];
__device__ __align__(128) __half hMem[(size_t)2 * Bn * 512];   // [src_mem; dst_mem]
__device__ __align__(128) __half hH1[(size_t)2 * Bn * 512];    // [H1a; H1b]
__device__ __align__(128) __half hM[(size_t)2 * Bn * 512];     // [Ms; Md]
__device__ __align__(128) __half hGh[(size_t)2 * Bn * 1536];   // [gh_s; gh_d]
__device__ __align__(128) __half hGi[(size_t)2 * Bn * 1536];   // [gi_d; gi_s]
__device__ __align__(128) __half hC[(size_t)2 * Bn * 1024];    // [Cs; Cd]
__device__ __align__(128) __half hW1s[1024 * K1];              // [W1; W1perm]
__device__ __align__(128) __half hW2[512 * 512];
__device__ __align__(128) __half hWih[1536 * 512];
__device__ __align__(128) __half hWhh[1536 * 512];
__device__ __align__(128) __half hWo[512 * 1024];
__device__ float dB1[1024];

// ---------- asm ----------
__device__ __forceinline__ uint32_t smem_u32(const void* p) {
    uint32_t a;
    asm("{ .reg .u64 t; cvta.to.shared.u64 t, %1; cvt.u32.u64 %0, t; }" : "=r"(a) : "l"(p));
    return a;
}
__device__ __forceinline__ void cp16(uint32_t d, const void* s) {
    asm volatile("cp.async.cg.shared.global [%0], [%1], 16;" :: "r"(d), "l"(s) : "memory");
}
__device__ __forceinline__ void cp16p(uint32_t d, const void* s, bool pred) {
    if (pred)
        asm volatile("cp.async.cg.shared.global [%0], [%1], 16;" :: "r"(d), "l"(s) : "memory");
}
#define CP_COMMIT() asm volatile("cp.async.commit_group;" ::: "memory")
#define CP_WAIT1() asm volatile("cp.async.wait_group 1;" ::: "memory")
#define LDSM4(r, a) \
    asm volatile("ldmatrix.sync.aligned.m8n8.x4.shared.b16 {%0,%1,%2,%3},[%4];" \
        : "=r"((r)[0]), "=r"((r)[1]), "=r"((r)[2]), "=r"((r)[3]) : "r"(a))
#define LDSM4B(r0, r1, a) \
    asm volatile("ldmatrix.sync.aligned.m8n8.x4.shared.b16 {%0,%1,%2,%3},[%4];" \
        : "=r"((r0)[0]), "=r"((r0)[1]), "=r"((r1)[0]), "=r"((r1)[1]) : "r"(a))
#define MMAH(d, a, b) \
    asm volatile("mma.sync.aligned.m16n8k16.row.col.f32.f16.f16.f32 " \
        "{%0,%1,%2,%3},{%4,%5,%6,%7},{%8,%9},{%0,%1,%2,%3};" \
        : "+f"((d)[0]), "+f"((d)[1]), "+f"((d)[2]), "+f"((d)[3]) \
        : "r"((a)[0]), "r"((a)[1]), "r"((a)[2]), "r"((a)[3]), "r"((b)[0]), "r"((b)[1]))

// ---------- fp16 GEMM: C = A @ B^T + bias ----------
// Block 128x128, BK=64 (128B rows), 4 warps (64x64), 3-stage cp.async,
// XOR swizzle (chunk c of row r at r*128 + 16*(c^(r&7))). Single-buffered
// fragments (reg budget); stage kt+2 cp.async interleaved across ks-steps.
// mode 0: fp32 C; 1: relu->half; 2: ->half; 3: relu->half row-split dual out.
#define A_B 16384
#define STG (2 * A_B)
#define GSMEM (3 * STG)

__global__ void __launch_bounds__(128, 2)
hgemm(const __half* __restrict__ A, int lda,
      const __half* __restrict__ B, int ldb, int K,
      const float* __restrict__ bias,
      float* __restrict__ C, int ldc,
      __half* __restrict__ H, int ldo, int mode)
{
    extern __shared__ __align__(128) char smx[];
    const uint32_t sbase = smem_u32(smx);
    const int tid = threadIdx.x, wid = tid >> 5, lane = tid & 31;
    const int wr = wid >> 1, wc = wid & 1;
    const size_t rowA = (size_t)blockIdx.y * 128;
    const int colB = blockIdx.x * 128;
    const __half* pA = A + (rowA + tid) * lda;
    const __half* pB = B + ((size_t)colB + tid) * ldb;
    const int key = tid & 7;

    float acc[4][8][4];
#pragma unroll
    for (int i = 0; i < 4; i++)
#pragma unroll
        for (int j = 0; j < 8; j++) {
            acc[i][j][0] = 0.f; acc[i][j][1] = 0.f;
            acc[i][j][2] = 0.f; acc[i][j][3] = 0.f;
        }

    const int nk = K >> 6;
    auto load_stage = [&](int kt, int s) {
        const int kc = kt << 6;
        uint32_t dA = sbase + s * STG + tid * 128;
#pragma unroll
        for (int c = 0; c < 8; c++) {
            cp16(dA + 16 * (c ^ key), pA + kc + c * 8);
            cp16(dA + A_B + 16 * (c ^ key), pB + kc + c * 8);
        }
        CP_COMMIT();
    };
    load_stage(0, 0);
    load_stage(1, 1);

    const int g = lane >> 3, r8 = lane & 7;
    const uint32_t aRowOff = (uint32_t)((wr * 64 + (g & 1) * 8 + r8) * 128);
    const uint32_t bRowOff = (uint32_t)((wc * 64 + (g >> 1) * 8 + r8) * 128) + A_B;
    const int aCk = g >> 1, bCk = g & 1;

    int s_cur = 0, s_nxt = 2;
    for (int kt = 0; kt < nk; ++kt) {
        CP_WAIT1();
        __syncthreads();
        const uint32_t st = sbase + s_cur * STG;
        const bool pf = (kt + 2 < nk);
        const int kc2 = (kt + 2) << 6;
        const uint32_t dA = sbase + s_nxt * STG + tid * 128;
#pragma unroll
        for (int ks = 0; ks < 4; ks++) {
            uint32_t av[4][4], bv[8][2];
            const uint32_t ach = (uint32_t)(16 * ((2 * ks + aCk) ^ r8));
            const uint32_t bch = (uint32_t)(16 * ((2 * ks + bCk) ^ r8));
#pragma unroll
            for (int mt = 0; mt < 4; mt++)
                LDSM4(av[mt], st + aRowOff + (uint32_t)(mt * 2048) + ach);
#pragma unroll
            for (int np = 0; np < 4; np++)
                LDSM4B(bv[2 * np], bv[2 * np + 1],
                       st + bRowOff + (uint32_t)(np * 2048) + bch);
            // interleaved prefetch of stage kt+2: 4 cp.async per ks-step
            {
                const int c0 = 2 * ks, c1 = 2 * ks + 1;
                cp16p(dA + 16 * (c0 ^ key), pA + kc2 + c0 * 8, pf);
                cp16p(dA + 16 * (c1 ^ key), pA + kc2 + c1 * 8, pf);
                cp16p(dA + A_B + 16 * (c0 ^ key), pB + kc2 + c0 * 8, pf);
                cp16p(dA + A_B + 16 * (c1 ^ key), pB + kc2 + c1 * 8, pf);
            }
#pragma unroll
            for (int mt = 0; mt < 4; mt++)
#pragma unroll
                for (int nt = 0; nt < 8; nt++)
                    MMAH(acc[mt][nt], av[mt], bv[nt]);
        }
        CP_COMMIT();
        if (++s_cur == 3) s_cur = 0;
        if (++s_nxt == 3) s_nxt = 0;
    }

    __half* Hb = H;
    int cSub = 0;
    if (mode == 3 && colB >= 512) { Hb = H + (size_t)Bn * 512; cSub = 512; }
    const int doRelu = (mode == 1 || mode == 3);

#pragma unroll
    for (int mt = 0; mt < 4; mt++) {
        size_t r0 = rowA + wr * 64 + mt * 16 + (lane >> 2);
#pragma unroll
        for (int nt = 0; nt < 8; nt++) {
            int col = colB + wc * 64 + nt * 8 + (lane & 3) * 2;
            float b0 = bias[col], b1 = bias[col + 1];
            float v0 = acc[mt][nt][0] + b0, v1 = acc[mt][nt][1] + b1;
            float v2 = acc[mt][nt][2] + b0, v3 = acc[mt][nt][3] + b1;
            if (mode == 0) {
                *(float2*)(C + r0 * ldc + col) = make_float2(v0, v1);
                *(float2*)(C + (r0 + 8) * ldc + col) = make_float2(v2, v3);
            } else {
                if (doRelu) {
                    v0 = fmaxf(v0, 0.f); v1 = fmaxf(v1, 0.f);
                    v2 = fmaxf(v2, 0.f); v3 = fmaxf(v3, 0.f);
                }
                int cs = col - cSub;
                *(__half2*)(Hb + r0 * ldo + cs) = __floats2half2_rn(v0, v1);
                *(__half2*)(Hb + (r0 + 8) * ldo + cs) = __floats2half2_rn(v2, v3);
            }
        }
    }
}

// ---------- elementwise ----------
__global__ void conv_h(const float* __restrict__ w, __half* __restrict__ h, int n) {
    int i = blockIdx.x * blockDim.x + threadIdx.x;
    if (i < n / 2) {
        float2 v = *(const float2*)(w + 2 * i);
        *(__half2*)(h + 2 * i) = __floats2half2_rn(v.x, v.y);
    }
}

__global__ void w1_pack(const float* __restrict__ w1) {
    int i = blockIdx.x * blockDim.x + threadIdx.x;
    if (i >= 1024 * K1) return;
    int n = i / K1, k = i % K1;
    int src;
    if (n < 512) src = n * K1 + k;
    else {
        int kk = (k < 512) ? k + 512 : (k < 1024 ? k - 512 : k);
        src = (n - 512) * K1 + kk;
    }
    hW1s[i] = __float2half(w1[src]);
}

__global__ void b1_pack(const float* __restrict__ b) {
    int i = threadIdx.x + blockIdx.x * blockDim.x;
    if (i < 1024) dB1[i] = b[i & 511];
}

__global__ void gather_pack(const float* __restrict__ mem, const float* __restrict__ edge,
                            const float* __restrict__ ts, const float* __restrict__ tw,
                            const float* __restrict__ tb,
                            const int* __restrict__ sid, const int* __restrict__ did) {
    int row = blockIdx.x, t = threadIdx.x;   // 256
    size_t ra = (size_t)row * K1;
    int si = sid[row], di = did[row];
    float2 s2 = *(const float2*)(mem + (size_t)si * 512 + 2 * t);
    float2 d2 = *(const float2*)(mem + (size_t)di * 512 + 2 * t);
    float2 e2 = *(const float2*)(edge + (size_t)row * 512 + 2 * t);
    __half2 hs = __floats2half2_rn(s2.x, s2.y);
    __half2 hd = __floats2half2_rn(d2.x, d2.y);
    __half2 he = __floats2half2_rn(e2.x, e2.y);
    *(__half2*)(hX1a + ra + 2 * t) = hs;
    *(__half2*)(hX1a + ra + 512 + 2 * t) = hd;
    *(__half2*)(hX1a + ra + 1024 + 2 * t) = he;
    *(__half2*)(hMem + (size_t)row * 512 + 2 * t) = hs;
    *(__half2*)(hMem + (size_t)(Bn + row) * 512 + 2 * t) = hd;
    if (t < 64) {
        float tt = ts[row];
        float cx = cosf(tt * tw[2 * t] + tb[2 * t]);
        float cy = cosf(tt * tw[2 * t + 1] + tb[2 * t + 1]);
        *(__half2*)(hX1a + ra + 1536 + 2 * t) = __floats2half2_rn(cx, cy);
    }
}

__global__ void emb_pack(const float* __restrict__ se, const float* __restrict__ de) {
    int row = blockIdx.x, t = threadIdx.x;  // 256
    float2 a = *(const float2*)(se + (size_t)row * 512 + 2 * t);
    float2 b = *(const float2*)(de + (size_t)row * 512 + 2 * t);
    *(__half2*)(hC + (size_t)row * 1024 + 512 + 2 * t) = __floats2half2_rn(a.x, a.y);
    *(__half2*)(hC + (size_t)(Bn + row) * 1024 + 512 + 2 * t) = __floats2half2_rn(b.x, b.y);
}

__device__ __forceinline__ float sigf(float x) { return 1.0f / (1.0f + expf(-x)); }
__device__ __forceinline__ float4 ld4h(const __half* p) {
    __half2 a = *(const __half2*)p, b = *(const __half2*)(p + 2);
    float2 fa = __half22float2(a), fb = __half22float2(b);
    return make_float4(fa.x, fa.y, fb.x, fb.y);
}

__global__ void gru_scatter(const __half* __restrict__ gi, const __half* __restrict__ gh,
                            const float* __restrict__ mem, const int* __restrict__ ids,
                            __half* __restrict__ ch, float* __restrict__ out_mem) {
    int row = blockIdx.x, j = threadIdx.x * 4, id = ids[row];
    size_t b3 = (size_t)row * 1536;
    float4 ir = ld4h(gi + b3 + j);
    float4 hr = ld4h(gh + b3 + j);
    float4 iz = ld4h(gi + b3 + 512 + j);
    float4 hz = ld4h(gh + b3 + 512 + j);
    float4 in4 = ld4h(gi + b3 + 1024 + j);
    float4 hn = ld4h(gh + b3 + 1024 + j);
    float4 hv = *(const float4*)(mem + (size_t)id * 512 + j);
    float4 u;
    { float r = sigf(ir.x + hr.x), z = sigf(iz.x + hz.x);
      float n = tanhf(in4.x + r * hn.x); u.x = (1.f - z) * n + z * hv.x; }
    { float r = sigf(ir.y + hr.y), z = sigf(iz.y + hz.y);
      float n = tanhf(in4.y + r * hn.y); u.y = (1.f - z) * n + z * hv.y; }
    { float r = sigf(ir.z + hr.z), z = sigf(iz.z + hz.z);
      float n = tanhf(in4.z + r * hn.z); u.z = (1.f - z) * n + z * hv.z; }
    { float r = sigf(ir.w + hr.w), z = sigf(iz.w + hz.w);
      float n = tanhf(in4.w + r * hn.w); u.w = (1.f - z) * n + z * hv.w; }
    *(float4*)(out_mem + (size_t)id * 512 + j) = u;
    size_t cb = (size_t)row * 1024 + j;
    *(__half2*)(ch + cb) = __floats2half2_rn(u.x, u.y);
    *(__half2*)(ch + cb + 2) = __floats2half2_rn(u.z, u.w);
}

// ---------- launch ----------
extern "C" void kernel_launch(void* const* d_in, const int* in_sizes, int n_in,
                              void* d_out, int out_size) {
    const float* src_emb  = (const float*)d_in[0];
    const float* dst_emb  = (const float*)d_in[1];
    const float* edge     = (const float*)d_in[2];
    const float* ts       = (const float*)d_in[3];
    const float* memory   = (const float*)d_in[4];
    const float* time_w   = (const float*)d_in[5];
    const float* time_b   = (const float*)d_in[6];
    const float* msg_w1   = (const float*)d_in[7];
    const float* msg_b1   = (const float*)d_in[8];
    const float* msg_w2   = (const float*)d_in[9];
    const float* msg_b2   = (const float*)d_in[10];
    const float* gru_w_ih = (const float*)d_in[11];
    const float* gru_w_hh = (const float*)d_in[12];
    const float* gru_b_ih = (const float*)d_in[13];
    const float* gru_b_hh = (const float*)d_in[14];
    const float* out_w    = (const float*)d_in[15];
    const float* out_b    = (const float*)d_in[16];
    const int*   src_ids  = (const int*)d_in[17];
    const int*   dst_ids  = (const int*)d_in[18];

    float* out_y = (float*)d_out;
    float* out_mem = out_y + (size_t)2 * Bn * 512;

    cudaFuncSetAttribute(hgemm, cudaFuncAttributeMaxDynamicSharedMemorySize, GSMEM);

#define SH(p, g) __half* p; cudaGetSymbolAddress((void**)&p, g)
#define SF(p, g) float* p; cudaGetSymbolAddress((void**)&p, g)
    SH(pXa, hX1a); SH(pMem, hMem); SH(pH1, hH1); SH(pM, hM); SH(pC, hC);
    SH(pGh, hGh); SH(pGi, hGi);
    SH(pW1s, hW1s); SH(pW2, hW2); SH(pWih, hWih); SH(pWhh, hWhh); SH(pWo, hWo);
    SF(pB1, dB1);
#undef SH
#undef SF

    cudaMemcpyAsync(out_mem, memory, (size_t)Nn * 512 * sizeof(float),
                    cudaMemcpyDeviceToDevice, 0);

    #define CVT(src, dst, n) conv_h<<<((n) / 2 + 255) / 256, 256>>>(src, dst, n)

    w1_pack<<<(1024 * K1 + 255) / 256, 256>>>(msg_w1);
    b1_pack<<<4, 256>>>(msg_b1);
    gather_pack<<<Bn, 256>>>(memory, edge, ts, time_w, time_b, src_ids, dst_ids);
    CVT(gru_w_hh, pWhh, 1536 * 512);

    // layer1 fused: [H1a|H1b] <- X1a @ [W1;W1p]^T, relu, row-split output
    hgemm<<<dim3(8, Bn / 128), 128, GSMEM>>>(pXa, K1, pW1s, K1, K1, pB1,
                                             (float*)0, 0, pH1, 512, 3);
    // gh: [gh_s; gh_d] <- [src_mem; dst_mem] @ Whh^T (fp16 out)
    hgemm<<<dim3(12, 2 * Bn / 128), 128, GSMEM>>>(pMem, 512, pWhh, 512, 512,
                                                  gru_b_hh, (float*)0, 0, pGh, 1536, 2);
    CVT(msg_w2, pW2, 512 * 512);
    // msg2: [Ms; Md] <- [H1a; H1b] @ W2^T
    hgemm<<<dim3(4, 2 * Bn / 128), 128, GSMEM>>>(pH1, 512, pW2, 512, 512,
                                                 msg_b2, (float*)0, 0, pM, 512, 2);
    CVT(gru_w_ih, pWih, 1536 * 512);
    // gi: rows 0:Bn = Ms@Wih (gi_dst), Bn:2Bn = Md@Wih (gi_src) (fp16 out)
    hgemm<<<dim3(12, 2 * Bn / 128), 128, GSMEM>>>(pM, 512, pWih, 512, 512,
                                                  gru_b_ih, (float*)0, 0, pGi, 1536, 2);
    emb_pack<<<Bn, 256>>>(src_emb, dst_emb);
    gru_scatter<<<Bn, 128>>>(pGi + (size_t)Bn * 1536, pGh, memory, src_ids,
                             pC, out_mem);
    gru_scatter<<<Bn, 128>>>(pGi, pGh + (size_t)Bn * 1536, memory, dst_ids,
                             pC + (size_t)Bn * 1024, out_mem);
    CVT(out_w, pWo, 512 * 1024);
    // output projection: [2Bn,512] directly into d_out
    hgemm<<<dim3(4, 2 * Bn / 128), 128, GSMEM>>>(pC, 1024, pWo, 1024, 1024,
                                                 out_b, out_y, 512, (__half*)0, 0, 0);
}

// round 16
// speedup vs baseline: 1.2325x; 1.0759x over previous
#include <cuda_runtime.h>
#include <cuda_fp16.h>
#include <math.h>
#include <stdint.h>

#define Bn 65536
#define K1 1664
#define Nn 200000

// ---------- scratch ----------
__device__ __align__(128) __half hX1a[(size_t)Bn * K1];
__device__ __align__(128) __half hMem[(size_t)2 * Bn * 512];   // [src_mem; dst_mem]
__device__ __align__(128) __half hH1[(size_t)2 * Bn * 512];    // [H1a; H1b]
__device__ __align__(128) __half hGh[(size_t)2 * Bn * 1536];   // [gh_s; gh_d]
__device__ __align__(128) __half hGi[(size_t)2 * Bn * 1536];   // [gi_d; gi_s]
__device__ __align__(128) __half hC[(size_t)2 * Bn * 1024];    // [Cs; Cd]
__device__ __align__(128) __half hW1s[1024 * K1];              // [W1; W1perm]
__device__ __align__(128) __half hW2T[512 * 512];              // W2 transposed
__device__ __align__(128) __half hWih[1536 * 512];
__device__ __align__(128) __half hWc[1536 * 512];              // Wih @ W2
__device__ __align__(128) __half hWhh[1536 * 512];
__device__ __align__(128) __half hWo[512 * 1024];
__device__ float dB1[1024];
__device__ float dBc[1536];
__device__ float dZero[512];   // zero-initialized

// ---------- asm ----------
__device__ __forceinline__ uint32_t smem_u32(const void* p) {
    uint32_t a;
    asm("{ .reg .u64 t; cvta.to.shared.u64 t, %1; cvt.u32.u64 %0, t; }" : "=r"(a) : "l"(p));
    return a;
}
__device__ __forceinline__ void cp16(uint32_t d, const void* s) {
    asm volatile("cp.async.cg.shared.global [%0], [%1], 16;" :: "r"(d), "l"(s) : "memory");
}
__device__ __forceinline__ void cp16p(uint32_t d, const void* s, bool pred) {
    if (pred)
        asm volatile("cp.async.cg.shared.global [%0], [%1], 16;" :: "r"(d), "l"(s) : "memory");
}
#define CP_COMMIT() asm volatile("cp.async.commit_group;" ::: "memory")
#define CP_WAIT1() asm volatile("cp.async.wait_group 1;" ::: "memory")
#define LDSM4(r, a) \
    asm volatile("ldmatrix.sync.aligned.m8n8.x4.shared.b16 {%0,%1,%2,%3},[%4];" \
        : "=r"((r)[0]), "=r"((r)[1]), "=r"((r)[2]), "=r"((r)[3]) : "r"(a))
#define LDSM4B(r0, r1, a) \
    asm volatile("ldmatrix.sync.aligned.m8n8.x4.shared.b16 {%0,%1,%2,%3},[%4];" \
        : "=r"((r0)[0]), "=r"((r0)[1]), "=r"((r1)[0]), "=r"((r1)[1]) : "r"(a))
#define MMAH(d, a, b) \
    asm volatile("mma.sync.aligned.m16n8k16.row.col.f32.f16.f16.f32 " \
        "{%0,%1,%2,%3},{%4,%5,%6,%7},{%8,%9},{%0,%1,%2,%3};" \
        : "+f"((d)[0]), "+f"((d)[1]), "+f"((d)[2]), "+f"((d)[3]) \
        : "r"((a)[0]), "r"((a)[1]), "r"((a)[2]), "r"((a)[3]), "r"((b)[0]), "r"((b)[1]))

// ---------- fp16 GEMM: C = A @ B^T + bias (proven R14 kernel) ----------
#define A_B 16384
#define STG (2 * A_B)
#define GSMEM (3 * STG)

__global__ void __launch_bounds__(128, 2)
hgemm(const __half* __restrict__ A, int lda,
      const __half* __restrict__ B, int ldb, int K,
      const float* __restrict__ bias,
      float* __restrict__ C, int ldc,
      __half* __restrict__ H, int ldo, int mode)
{
    extern __shared__ __align__(128) char smx[];
    const uint32_t sbase = smem_u32(smx);
    const int tid = threadIdx.x, wid = tid >> 5, lane = tid & 31;
    const int wr = wid >> 1, wc = wid & 1;
    const size_t rowA = (size_t)blockIdx.y * 128;
    const int colB = blockIdx.x * 128;
    const __half* pA = A + (rowA + tid) * lda;
    const __half* pB = B + ((size_t)colB + tid) * ldb;
    const int key = tid & 7;

    float acc[4][8][4];
#pragma unroll
    for (int i = 0; i < 4; i++)
#pragma unroll
        for (int j = 0; j < 8; j++) {
            acc[i][j][0] = 0.f; acc[i][j][1] = 0.f;
            acc[i][j][2] = 0.f; acc[i][j][3] = 0.f;
        }

    const int nk = K >> 6;
    auto load_stage = [&](int kt, int s) {
        const int kc = kt << 6;
        uint32_t dA = sbase + s * STG + tid * 128;
#pragma unroll
        for (int c = 0; c < 8; c++) {
            cp16(dA + 16 * (c ^ key), pA + kc + c * 8);
            cp16(dA + A_B + 16 * (c ^ key), pB + kc + c * 8);
        }
        CP_COMMIT();
    };
    load_stage(0, 0);
    load_stage(1, 1);

    const int g = lane >> 3, r8 = lane & 7;
    const uint32_t aRowOff = (uint32_t)((wr * 64 + (g & 1) * 8 + r8) * 128);
    const uint32_t bRowOff = (uint32_t)((wc * 64 + (g >> 1) * 8 + r8) * 128) + A_B;
    const int aCk = g >> 1, bCk = g & 1;

    int s_cur = 0, s_nxt = 2;
    for (int kt = 0; kt < nk; ++kt) {
        CP_WAIT1();
        __syncthreads();
        const uint32_t st = sbase + s_cur * STG;
        const bool pf = (kt + 2 < nk);
        const int kc2 = (kt + 2) << 6;
        const uint32_t dA = sbase + s_nxt * STG + tid * 128;
#pragma unroll
        for (int ks = 0; ks < 4; ks++) {
            uint32_t av[4][4], bv[8][2];
            const uint32_t ach = (uint32_t)(16 * ((2 * ks + aCk) ^ r8));
            const uint32_t bch = (uint32_t)(16 * ((2 * ks + bCk) ^ r8));
#pragma unroll
            for (int mt = 0; mt < 4; mt++)
                LDSM4(av[mt], st + aRowOff + (uint32_t)(mt * 2048) + ach);
#pragma unroll
            for (int np = 0; np < 4; np++)
                LDSM4B(bv[2 * np], bv[2 * np + 1],
                       st + bRowOff + (uint32_t)(np * 2048) + bch);
            {
                const int c0 = 2 * ks, c1 = 2 * ks + 1;
                cp16p(dA + 16 * (c0 ^ key), pA + kc2 + c0 * 8, pf);
                cp16p(dA + 16 * (c1 ^ key), pA + kc2 + c1 * 8, pf);
                cp16p(dA + A_B + 16 * (c0 ^ key), pB + kc2 + c0 * 8, pf);
                cp16p(dA + A_B + 16 * (c1 ^ key), pB + kc2 + c1 * 8, pf);
            }
#pragma unroll
            for (int mt = 0; mt < 4; mt++)
#pragma unroll
                for (int nt = 0; nt < 8; nt++)
                    MMAH(acc[mt][nt], av[mt], bv[nt]);
        }
        CP_COMMIT();
        if (++s_cur == 3) s_cur = 0;
        if (++s_nxt == 3) s_nxt = 0;
    }

    __half* Hb = H;
    int cSub = 0;
    if (mode == 3 && colB >= 512) { Hb = H + (size_t)Bn * 512; cSub = 512; }
    const int doRelu = (mode == 1 || mode == 3);

#pragma unroll
    for (int mt = 0; mt < 4; mt++) {
        size_t r0 = rowA + wr * 64 + mt * 16 + (lane >> 2);
#pragma unroll
        for (int nt = 0; nt < 8; nt++) {
            int col = colB + wc * 64 + nt * 8 + (lane & 3) * 2;
            float b0 = bias[col], b1 = bias[col + 1];
            float v0 = acc[mt][nt][0] + b0, v1 = acc[mt][nt][1] + b1;
            float v2 = acc[mt][nt][2] + b0, v3 = acc[mt][nt][3] + b1;
            if (mode == 0) {
                *(float2*)(C + r0 * ldc + col) = make_float2(v0, v1);
                *(float2*)(C + (r0 + 8) * ldc + col) = make_float2(v2, v3);
            } else {
                if (doRelu) {
                    v0 = fmaxf(v0, 0.f); v1 = fmaxf(v1, 0.f);
                    v2 = fmaxf(v2, 0.f); v3 = fmaxf(v3, 0.f);
                }
                int cs = col - cSub;
                *(__half2*)(Hb + r0 * ldo + cs) = __floats2half2_rn(v0, v1);
                *(__half2*)(Hb + (r0 + 8) * ldo + cs) = __floats2half2_rn(v2, v3);
            }
        }
    }
}

// ---------- elementwise ----------
__global__ void conv_h(const float* __restrict__ w, __half* __restrict__ h, int n) {
    int i = blockIdx.x * blockDim.x + threadIdx.x;
    if (i < n / 2) {
        float2 v = *(const float2*)(w + 2 * i);
        *(__half2*)(h + 2 * i) = __floats2half2_rn(v.x, v.y);
    }
}

// W2T[j,k] = W2[k,j], fp32 -> fp16
__global__ void w2t_pack(const float* __restrict__ w2) {
    int i = blockIdx.x * blockDim.x + threadIdx.x;   // over 512*512
    if (i >= 512 * 512) return;
    int j = i >> 9, k = i & 511;
    hW2T[i] = __float2half(w2[k * 512 + j]);
}

// bc = Wih @ b2 + b_ih  (one block per row)
__global__ void bc_pack(const float* __restrict__ wih, const float* __restrict__ b2,
                        const float* __restrict__ bih) {
    __shared__ float sm[4];
    int row = blockIdx.x, t = threadIdx.x;  // 128 thr
    const float* wr = wih + (size_t)row * 512;
    float s = 0.f;
    for (int k = t; k < 512; k += 128) s += wr[k] * b2[k];
#pragma unroll
    for (int o = 16; o; o >>= 1) s += __shfl_xor_sync(~0u, s, o);
    if ((t & 31) == 0) sm[t >> 5] = s;
    __syncthreads();
    if (t == 0) dBc[row] = sm[0] + sm[1] + sm[2] + sm[3] + bih[row];
}

__global__ void w1_pack(const float* __restrict__ w1) {
    int i = blockIdx.x * blockDim.x + threadIdx.x;
    if (i >= 1024 * K1) return;
    int n = i / K1, k = i % K1;
    int src;
    if (n < 512) src = n * K1 + k;
    else {
        int kk = (k < 512) ? k + 512 : (k < 1024 ? k - 512 : k);
        src = (n - 512) * K1 + kk;
    }
    hW1s[i] = __float2half(w1[src]);
}

__global__ void b1_pack(const float* __restrict__ b) {
    int i = threadIdx.x + blockIdx.x * blockDim.x;
    if (i < 1024) dB1[i] = b[i & 511];
}

__global__ void gather_pack(const float* __restrict__ mem, const float* __restrict__ edge,
                            const float* __restrict__ ts, const float* __restrict__ tw,
                            const float* __restrict__ tb,
                            const int* __restrict__ sid, const int* __restrict__ did) {
    int row = blockIdx.x, t = threadIdx.x;   // 256
    size_t ra = (size_t)row * K1;
    int si = sid[row], di = did[row];
    float2 s2 = *(const float2*)(mem + (size_t)si * 512 + 2 * t);
    float2 d2 = *(const float2*)(mem + (size_t)di * 512 + 2 * t);
    float2 e2 = *(const float2*)(edge + (size_t)row * 512 + 2 * t);
    __half2 hs = __floats2half2_rn(s2.x, s2.y);
    __half2 hd = __floats2half2_rn(d2.x, d2.y);
    __half2 he = __floats2half2_rn(e2.x, e2.y);
    *(__half2*)(hX1a + ra + 2 * t) = hs;
    *(__half2*)(hX1a + ra + 512 + 2 * t) = hd;
    *(__half2*)(hX1a + ra + 1024 + 2 * t) = he;
    *(__half2*)(hMem + (size_t)row * 512 + 2 * t) = hs;
    *(__half2*)(hMem + (size_t)(Bn + row) * 512 + 2 * t) = hd;
    if (t < 64) {
        float tt = ts[row];
        float cx = cosf(tt * tw[2 * t] + tb[2 * t]);
        float cy = cosf(tt * tw[2 * t + 1] + tb[2 * t + 1]);
        *(__half2*)(hX1a + ra + 1536 + 2 * t) = __floats2half2_rn(cx, cy);
    }
}

__global__ void emb_pack(const float* __restrict__ se, const float* __restrict__ de) {
    int row = blockIdx.x, t = threadIdx.x;  // 256
    float2 a = *(const float2*)(se + (size_t)row * 512 + 2 * t);
    float2 b = *(const float2*)(de + (size_t)row * 512 + 2 * t);
    *(__half2*)(hC + (size_t)row * 1024 + 512 + 2 * t) = __floats2half2_rn(a.x, a.y);
    *(__half2*)(hC + (size_t)(Bn + row) * 1024 + 512 + 2 * t) = __floats2half2_rn(b.x, b.y);
}

__device__ __forceinline__ float sigf(float x) { return 1.0f / (1.0f + expf(-x)); }
__device__ __forceinline__ float4 ld4h(const __half* p) {
    __half2 a = *(const __half2*)p, b = *(const __half2*)(p + 2);
    float2 fa = __half22float2(a), fb = __half22float2(b);
    return make_float4(fa.x, fa.y, fb.x, fb.y);
}

__global__ void gru_scatter(const __half* __restrict__ gi, const __half* __restrict__ gh,
                            const float* __restrict__ mem, const int* __restrict__ ids,
                            __half* __restrict__ ch, float* __restrict__ out_mem) {
    int row = blockIdx.x, j = threadIdx.x * 4, id = ids[row];
    size_t b3 = (size_t)row * 1536;
    float4 ir = ld4h(gi + b3 + j);
    float4 hr = ld4h(gh + b3 + j);
    float4 iz = ld4h(gi + b3 + 512 + j);
    float4 hz = ld4h(gh + b3 + 512 + j);
    float4 in4 = ld4h(gi + b3 + 1024 + j);
    float4 hn = ld4h(gh + b3 + 1024 + j);
    float4 hv = *(const float4*)(mem + (size_t)id * 512 + j);
    float4 u;
    { float r = sigf(ir.x + hr.x), z = sigf(iz.x + hz.x);
      float n = tanhf(in4.x + r * hn.x); u.x = (1.f - z) * n + z * hv.x; }
    { float r = sigf(ir.y + hr.y), z = sigf(iz.y + hz.y);
      float n = tanhf(in4.y + r * hn.y); u.y = (1.f - z) * n + z * hv.y; }
    { float r = sigf(ir.z + hr.z), z = sigf(iz.z + hz.z);
      float n = tanhf(in4.z + r * hn.z); u.z = (1.f - z) * n + z * hv.z; }
    { float r = sigf(ir.w + hr.w), z = sigf(iz.w + hz.w);
      float n = tanhf(in4.w + r * hn.w); u.w = (1.f - z) * n + z * hv.w; }
    *(float4*)(out_mem + (size_t)id * 512 + j) = u;
    size_t cb = (size_t)row * 1024 + j;
    *(__half2*)(ch + cb) = __floats2half2_rn(u.x, u.y);
    *(__half2*)(ch + cb + 2) = __floats2half2_rn(u.z, u.w);
}

// ---------- launch ----------
extern "C" void kernel_launch(void* const* d_in, const int* in_sizes, int n_in,
                              void* d_out, int out_size) {
    const float* src_emb  = (const float*)d_in[0];
    const float* dst_emb  = (const float*)d_in[1];
    const float* edge     = (const float*)d_in[2];
    const float* ts       = (const float*)d_in[3];
    const float* memory   = (const float*)d_in[4];
    const float* time_w   = (const float*)d_in[5];
    const float* time_b   = (const float*)d_in[6];
    const float* msg_w1   = (const float*)d_in[7];
    const float* msg_b1   = (const float*)d_in[8];
    const float* msg_w2   = (const float*)d_in[9];
    const float* msg_b2   = (const float*)d_in[10];
    const float* gru_w_ih = (const float*)d_in[11];
    const float* gru_w_hh = (const float*)d_in[12];
    const float* gru_b_ih = (const float*)d_in[13];
    const float* gru_b_hh = (const float*)d_in[14];
    const float* out_w    = (const float*)d_in[15];
    const float* out_b    = (const float*)d_in[16];
    const int*   src_ids  = (const int*)d_in[17];
    const int*   dst_ids  = (const int*)d_in[18];

    float* out_y = (float*)d_out;
    float* out_mem = out_y + (size_t)2 * Bn * 512;

    cudaFuncSetAttribute(hgemm, cudaFuncAttributeMaxDynamicSharedMemorySize, GSMEM);

#define SH(p, g) __half* p; cudaGetSymbolAddress((void**)&p, g)
#define SF(p, g) float* p; cudaGetSymbolAddress((void**)&p, g)
    SH(pXa, hX1a); SH(pMem, hMem); SH(pH1, hH1); SH(pC, hC);
    SH(pGh, hGh); SH(pGi, hGi);
    SH(pW1s, hW1s); SH(pW2T, hW2T); SH(pWih, hWih); SH(pWc, hWc);
    SH(pWhh, hWhh); SH(pWo, hWo);
    SF(pB1, dB1); SF(pBc, dBc); SF(pZero, dZero);
#undef SH
#undef SF

    cudaMemcpyAsync(out_mem, memory, (size_t)Nn * 512 * sizeof(float),
                    cudaMemcpyDeviceToDevice, 0);

    #define CVT(src, dst, n) conv_h<<<((n) / 2 + 255) / 256, 256>>>(src, dst, n)

    w1_pack<<<(1024 * K1 + 255) / 256, 256>>>(msg_w1);
    b1_pack<<<4, 256>>>(msg_b1);
    gather_pack<<<Bn, 256>>>(memory, edge, ts, time_w, time_b, src_ids, dst_ids);
    CVT(gru_w_hh, pWhh, 1536 * 512);
    // composed gi weights: Wc = Wih @ W2, bc = Wih @ b2 + b_ih
    w2t_pack<<<(512 * 512 + 255) / 256, 256>>>(msg_w2);
    CVT(gru_w_ih, pWih, 1536 * 512);
    bc_pack<<<1536, 128>>>(gru_w_ih, msg_b2, gru_b_ih);
    hgemm<<<dim3(4, 12), 128, GSMEM>>>(pWih, 512, pW2T, 512, 512, pZero,
                                       (float*)0, 0, pWc, 512, 2);

    // layer1 fused: [H1a|H1b] <- X1a @ [W1;W1p]^T, relu, row-split output
    hgemm<<<dim3(8, Bn / 128), 128, GSMEM>>>(pXa, K1, pW1s, K1, K1, pB1,
                                             (float*)0, 0, pH1, 512, 3);
    // gh: [gh_s; gh_d] <- [src_mem; dst_mem] @ Whh^T (fp16 out)
    hgemm<<<dim3(12, 2 * Bn / 128), 128, GSMEM>>>(pMem, 512, pWhh, 512, 512,
                                                  gru_b_hh, (float*)0, 0, pGh, 1536, 2);
    // gi (msg2 fused): rows 0:Bn = H1a@Wc (gi_dst), Bn:2Bn = H1b@Wc (gi_src)
    hgemm<<<dim3(12, 2 * Bn / 128), 128, GSMEM>>>(pH1, 512, pWc, 512, 512,
                                                  pBc, (float*)0, 0, pGi, 1536, 2);
    emb_pack<<<Bn, 256>>>(src_emb, dst_emb);
    gru_scatter<<<Bn, 128>>>(pGi + (size_t)Bn * 1536, pGh, memory, src_ids,
                             pC, out_mem);
    gru_scatter<<<Bn, 128>>>(pGi, pGh + (size_t)Bn * 1536, memory, dst_ids,
                             pC + (size_t)Bn * 1024, out_mem);
    CVT(out_w, pWo, 512 * 1024);
    // output projection: [2Bn,512] directly into d_out
    hgemm<<<dim3(4, 2 * Bn / 128), 128, GSMEM>>>(pC, 1024, pWo, 1024, 1024,
                                                 out_b, out_y, 512, (__half*)0, 0, 0);
}

// round 17
// speedup vs baseline: 1.2388x; 1.0052x over previous
#include <cuda_runtime.h>
#include <cuda_fp16.h>
#include <math.h>
#include <stdint.h>

#define Bn 65536
#define K1 1664
#define Nn 200000

// ---------- scratch ----------
__device__ __align__(128) __half hX1a[(size_t)Bn * K1];
__device__ __align__(128) __half hMem[(size_t)2 * Bn * 512];   // [src_mem; dst_mem]
__device__ __align__(128) __half hH1[(size_t)2 * Bn * 512];    // [H1a; H1b]
__device__ __align__(128) __half hGh[(size_t)2 * Bn * 1536];   // [gh_s; gh_d]
__device__ __align__(128) __half hGi[(size_t)2 * Bn * 1536];   // [gi_d; gi_s]
__device__ __align__(128) __half hC[(size_t)2 * Bn * 1024];    // [Cs; Cd]
__device__ __align__(128) __half hW1s[1024 * K1];              // [W1; W1perm]
__device__ __align__(128) __half hW2T[512 * 512];              // W2 transposed
__device__ __align__(128) __half hWih[1536 * 512];
__device__ __align__(128) __half hWc[1536 * 512];              // Wih @ W2
__device__ __align__(128) __half hWhh[1536 * 512];
__device__ __align__(128) __half hWo[512 * 1024];
__device__ float dB1[1024];
__device__ float dBc[1536];
__device__ float dZero[512];   // zero-initialized

// ---------- asm ----------
__device__ __forceinline__ uint32_t smem_u32(const void* p) {
    uint32_t a;
    asm("{ .reg .u64 t; cvta.to.shared.u64 t, %1; cvt.u32.u64 %0, t; }" : "=r"(a) : "l"(p));
    return a;
}
__device__ __forceinline__ void cp16(uint32_t d, const void* s) {
    asm volatile("cp.async.cg.shared.global [%0], [%1], 16;" :: "r"(d), "l"(s) : "memory");
}
__device__ __forceinline__ void cp16p(uint32_t d, const void* s, bool pred) {
    if (pred)
        asm volatile("cp.async.cg.shared.global [%0], [%1], 16;" :: "r"(d), "l"(s) : "memory");
}
#define CP_COMMIT() asm volatile("cp.async.commit_group;" ::: "memory")
#define CP_WAIT1() asm volatile("cp.async.wait_group 1;" ::: "memory")
#define LDSM4(r, a) \
    asm volatile("ldmatrix.sync.aligned.m8n8.x4.shared.b16 {%0,%1,%2,%3},[%4];" \
        : "=r"((r)[0]), "=r"((r)[1]), "=r"((r)[2]), "=r"((r)[3]) : "r"(a))
#define LDSM4B(r0, r1, a) \
    asm volatile("ldmatrix.sync.aligned.m8n8.x4.shared.b16 {%0,%1,%2,%3},[%4];" \
        : "=r"((r0)[0]), "=r"((r0)[1]), "=r"((r1)[0]), "=r"((r1)[1]) : "r"(a))
#define MMAH(d, a, b) \
    asm volatile("mma.sync.aligned.m16n8k16.row.col.f32.f16.f16.f32 " \
        "{%0,%1,%2,%3},{%4,%5,%6,%7},{%8,%9},{%0,%1,%2,%3};" \
        : "+f"((d)[0]), "+f"((d)[1]), "+f"((d)[2]), "+f"((d)[3]) \
        : "r"((a)[0]), "r"((a)[1]), "r"((a)[2]), "r"((a)[3]), "r"((b)[0]), "r"((b)[1]))

// ---------- fp16 GEMM (proven R14/R16 kernel) ----------
#define A_B 16384
#define STG (2 * A_B)
#define GSMEM (3 * STG)

__global__ void __launch_bounds__(128, 2)
hgemm(const __half* __restrict__ A, int lda,
      const __half* __restrict__ B, int ldb, int K,
      const float* __restrict__ bias,
      float* __restrict__ C, int ldc,
      __half* __restrict__ H, int ldo, int mode)
{
    extern __shared__ __align__(128) char smx[];
    const uint32_t sbase = smem_u32(smx);
    const int tid = threadIdx.x, wid = tid >> 5, lane = tid & 31;
    const int wr = wid >> 1, wc = wid & 1;
    const size_t rowA = (size_t)blockIdx.y * 128;
    const int colB = blockIdx.x * 128;
    const __half* pA = A + (rowA + tid) * lda;
    const __half* pB = B + ((size_t)colB + tid) * ldb;
    const int key = tid & 7;

    float acc[4][8][4];
#pragma unroll
    for (int i = 0; i < 4; i++)
#pragma unroll
        for (int j = 0; j < 8; j++) {
            acc[i][j][0] = 0.f; acc[i][j][1] = 0.f;
            acc[i][j][2] = 0.f; acc[i][j][3] = 0.f;
        }

    const int nk = K >> 6;
    auto load_stage = [&](int kt, int s) {
        const int kc = kt << 6;
        uint32_t dA = sbase + s * STG + tid * 128;
#pragma unroll
        for (int c = 0; c < 8; c++) {
            cp16(dA + 16 * (c ^ key), pA + kc + c * 8);
            cp16(dA + A_B + 16 * (c ^ key), pB + kc + c * 8);
        }
        CP_COMMIT();
    };
    load_stage(0, 0);
    load_stage(1, 1);

    const int g = lane >> 3, r8 = lane & 7;
    const uint32_t aRowOff = (uint32_t)((wr * 64 + (g & 1) * 8 + r8) * 128);
    const uint32_t bRowOff = (uint32_t)((wc * 64 + (g >> 1) * 8 + r8) * 128) + A_B;
    const int aCk = g >> 1, bCk = g & 1;

    int s_cur = 0, s_nxt = 2;
    for (int kt = 0; kt < nk; ++kt) {
        CP_WAIT1();
        __syncthreads();
        const uint32_t st = sbase + s_cur * STG;
        const bool pf = (kt + 2 < nk);
        const int kc2 = (kt + 2) << 6;
        const uint32_t dA = sbase + s_nxt * STG + tid * 128;
#pragma unroll
        for (int ks = 0; ks < 4; ks++) {
            uint32_t av[4][4], bv[8][2];
            const uint32_t ach = (uint32_t)(16 * ((2 * ks + aCk) ^ r8));
            const uint32_t bch = (uint32_t)(16 * ((2 * ks + bCk) ^ r8));
#pragma unroll
            for (int mt = 0; mt < 4; mt++)
                LDSM4(av[mt], st + aRowOff + (uint32_t)(mt * 2048) + ach);
#pragma unroll
            for (int np = 0; np < 4; np++)
                LDSM4B(bv[2 * np], bv[2 * np + 1],
                       st + bRowOff + (uint32_t)(np * 2048) + bch);
            {
                const int c0 = 2 * ks, c1 = 2 * ks + 1;
                cp16p(dA + 16 * (c0 ^ key), pA + kc2 + c0 * 8, pf);
                cp16p(dA + 16 * (c1 ^ key), pA + kc2 + c1 * 8, pf);
                cp16p(dA + A_B + 16 * (c0 ^ key), pB + kc2 + c0 * 8, pf);
                cp16p(dA + A_B + 16 * (c1 ^ key), pB + kc2 + c1 * 8, pf);
            }
#pragma unroll
            for (int mt = 0; mt < 4; mt++)
#pragma unroll
                for (int nt = 0; nt < 8; nt++)
                    MMAH(acc[mt][nt], av[mt], bv[nt]);
        }
        CP_COMMIT();
        if (++s_cur == 3) s_cur = 0;
        if (++s_nxt == 3) s_nxt = 0;
    }

    __half* Hb = H;
    int cSub = 0;
    if (mode == 3 && colB >= 512) { Hb = H + (size_t)Bn * 512; cSub = 512; }
    const int doRelu = (mode == 1 || mode == 3);

#pragma unroll
    for (int mt = 0; mt < 4; mt++) {
        size_t r0 = rowA + wr * 64 + mt * 16 + (lane >> 2);
#pragma unroll
        for (int nt = 0; nt < 8; nt++) {
            int col = colB + wc * 64 + nt * 8 + (lane & 3) * 2;
            float b0 = bias[col], b1 = bias[col + 1];
            float v0 = acc[mt][nt][0] + b0, v1 = acc[mt][nt][1] + b1;
            float v2 = acc[mt][nt][2] + b0, v3 = acc[mt][nt][3] + b1;
            if (mode == 0) {
                *(float2*)(C + r0 * ldc + col) = make_float2(v0, v1);
                *(float2*)(C + (r0 + 8) * ldc + col) = make_float2(v2, v3);
            } else {
                if (doRelu) {
                    v0 = fmaxf(v0, 0.f); v1 = fmaxf(v1, 0.f);
                    v2 = fmaxf(v2, 0.f); v3 = fmaxf(v3, 0.f);
                }
                int cs = col - cSub;
                *(__half2*)(Hb + r0 * ldo + cs) = __floats2half2_rn(v0, v1);
                *(__half2*)(Hb + (r0 + 8) * ldo + cs) = __floats2half2_rn(v2, v3);
            }
        }
    }
}

// ---------- elementwise ----------
__global__ void conv_h(const float* __restrict__ w, __half* __restrict__ h, int n) {
    int i = blockIdx.x * blockDim.x + threadIdx.x;
    if (i < n / 2) {
        float2 v = *(const float2*)(w + 2 * i);
        *(__half2*)(h + 2 * i) = __floats2half2_rn(v.x, v.y);
    }
}

__global__ void w2t_pack(const float* __restrict__ w2) {
    int i = blockIdx.x * blockDim.x + threadIdx.x;
    if (i >= 512 * 512) return;
    int j = i >> 9, k = i & 511;
    hW2T[i] = __float2half(w2[k * 512 + j]);
}

__global__ void bc_pack(const float* __restrict__ wih, const float* __restrict__ b2,
                        const float* __restrict__ bih) {
    __shared__ float sm[4];
    int row = blockIdx.x, t = threadIdx.x;  // 128 thr
    const float* wr = wih + (size_t)row * 512;
    float s = 0.f;
    for (int k = t; k < 512; k += 128) s += wr[k] * b2[k];
#pragma unroll
    for (int o = 16; o; o >>= 1) s += __shfl_xor_sync(~0u, s, o);
    if ((t & 31) == 0) sm[t >> 5] = s;
    __syncthreads();
    if (t == 0) dBc[row] = sm[0] + sm[1] + sm[2] + sm[3] + bih[row];
}

__global__ void w1_pack(const float* __restrict__ w1) {
    int i = blockIdx.x * blockDim.x + threadIdx.x;
    if (i >= 1024 * K1) return;
    int n = i / K1, k = i % K1;
    int src;
    if (n < 512) src = n * K1 + k;
    else {
        int kk = (k < 512) ? k + 512 : (k < 1024 ? k - 512 : k);
        src = (n - 512) * K1 + kk;
    }
    hW1s[i] = __float2half(w1[src]);
}

__global__ void b1_pack(const float* __restrict__ b) {
    int i = threadIdx.x + blockIdx.x * blockDim.x;
    if (i < 1024) dB1[i] = b[i & 511];
}

__global__ void gather_pack(const float* __restrict__ mem, const float* __restrict__ edge,
                            const float* __restrict__ ts, const float* __restrict__ tw,
                            const float* __restrict__ tb,
                            const int* __restrict__ sid, const int* __restrict__ did) {
    int row = blockIdx.x, t = threadIdx.x;   // 256
    size_t ra = (size_t)row * K1;
    int si = sid[row], di = did[row];
    float2 s2 = *(const float2*)(mem + (size_t)si * 512 + 2 * t);
    float2 d2 = *(const float2*)(mem + (size_t)di * 512 + 2 * t);
    float2 e2 = *(const float2*)(edge + (size_t)row * 512 + 2 * t);
    __half2 hs = __floats2half2_rn(s2.x, s2.y);
    __half2 hd = __floats2half2_rn(d2.x, d2.y);
    __half2 he = __floats2half2_rn(e2.x, e2.y);
    *(__half2*)(hX1a + ra + 2 * t) = hs;
    *(__half2*)(hX1a + ra + 512 + 2 * t) = hd;
    *(__half2*)(hX1a + ra + 1024 + 2 * t) = he;
    *(__half2*)(hMem + (size_t)row * 512 + 2 * t) = hs;
    *(__half2*)(hMem + (size_t)(Bn + row) * 512 + 2 * t) = hd;
    if (t < 64) {
        float tt = ts[row];
        float cx = cosf(tt * tw[2 * t] + tb[2 * t]);
        float cy = cosf(tt * tw[2 * t + 1] + tb[2 * t + 1]);
        *(__half2*)(hX1a + ra + 1536 + 2 * t) = __floats2half2_rn(cx, cy);
    }
}

__global__ void emb_pack(const float* __restrict__ se, const float* __restrict__ de) {
    int row = blockIdx.x, t = threadIdx.x;  // 256
    float2 a = *(const float2*)(se + (size_t)row * 512 + 2 * t);
    float2 b = *(const float2*)(de + (size_t)row * 512 + 2 * t);
    *(__half2*)(hC + (size_t)row * 1024 + 512 + 2 * t) = __floats2half2_rn(a.x, a.y);
    *(__half2*)(hC + (size_t)(Bn + row) * 1024 + 512 + 2 * t) = __floats2half2_rn(b.x, b.y);
}

__device__ __forceinline__ float sigf(float x) { return 1.0f / (1.0f + expf(-x)); }
__device__ __forceinline__ float4 ld4h(const __half* p) {
    __half2 a = *(const __half2*)p, b = *(const __half2*)(p + 2);
    float2 fa = __half22float2(a), fb = __half22float2(b);
    return make_float4(fa.x, fa.y, fb.x, fb.y);
}

__global__ void gru_scatter(const __half* __restrict__ gi, const __half* __restrict__ gh,
                            const float* __restrict__ mem, const int* __restrict__ ids,
                            __half* __restrict__ ch, float* __restrict__ out_mem) {
    int row = blockIdx.x, j = threadIdx.x * 4, id = ids[row];
    size_t b3 = (size_t)row * 1536;
    float4 ir = ld4h(gi + b3 + j);
    float4 hr = ld4h(gh + b3 + j);
    float4 iz = ld4h(gi + b3 + 512 + j);
    float4 hz = ld4h(gh + b3 + 512 + j);
    float4 in4 = ld4h(gi + b3 + 1024 + j);
    float4 hn = ld4h(gh + b3 + 1024 + j);
    float4 hv = *(const float4*)(mem + (size_t)id * 512 + j);
    float4 u;
    { float r = sigf(ir.x + hr.x), z = sigf(iz.x + hz.x);
      float n = tanhf(in4.x + r * hn.x); u.x = (1.f - z) * n + z * hv.x; }
    { float r = sigf(ir.y + hr.y), z = sigf(iz.y + hz.y);
      float n = tanhf(in4.y + r * hn.y); u.y = (1.f - z) * n + z * hv.y; }
    { float r = sigf(ir.z + hr.z), z = sigf(iz.z + hz.z);
      float n = tanhf(in4.z + r * hn.z); u.z = (1.f - z) * n + z * hv.z; }
    { float r = sigf(ir.w + hr.w), z = sigf(iz.w + hz.w);
      float n = tanhf(in4.w + r * hn.w); u.w = (1.f - z) * n + z * hv.w; }
    *(float4*)(out_mem + (size_t)id * 512 + j) = u;
    size_t cb = (size_t)row * 1024 + j;
    *(__half2*)(ch + cb) = __floats2half2_rn(u.x, u.y);
    *(__half2*)(ch + cb + 2) = __floats2half2_rn(u.z, u.w);
}

// ---------- launch ----------
extern "C" void kernel_launch(void* const* d_in, const int* in_sizes, int n_in,
                              void* d_out, int out_size) {
    const float* src_emb  = (const float*)d_in[0];
    const float* dst_emb  = (const float*)d_in[1];
    const float* edge     = (const float*)d_in[2];
    const float* ts       = (const float*)d_in[3];
    const float* memory   = (const float*)d_in[4];
    const float* time_w   = (const float*)d_in[5];
    const float* time_b   = (const float*)d_in[6];
    const float* msg_w1   = (const float*)d_in[7];
    const float* msg_b1   = (const float*)d_in[8];
    const float* msg_w2   = (const float*)d_in[9];
    const float* msg_b2   = (const float*)d_in[10];
    const float* gru_w_ih = (const float*)d_in[11];
    const float* gru_w_hh = (const float*)d_in[12];
    const float* gru_b_ih = (const float*)d_in[13];
    const float* gru_b_hh = (const float*)d_in[14];
    const float* out_w    = (const float*)d_in[15];
    const float* out_b    = (const float*)d_in[16];
    const int*   src_ids  = (const int*)d_in[17];
    const int*   dst_ids  = (const int*)d_in[18];

    float* out_y = (float*)d_out;
    float* out_mem = out_y + (size_t)2 * Bn * 512;

    static cudaStream_t s2 = 0;
    static cudaEvent_t ev0 = 0, evW = 0, evC = 0;
    if (!s2) {
        cudaStreamCreateWithFlags(&s2, cudaStreamNonBlocking);
        cudaEventCreateWithFlags(&ev0, cudaEventDisableTiming);
        cudaEventCreateWithFlags(&evW, cudaEventDisableTiming);
        cudaEventCreateWithFlags(&evC, cudaEventDisableTiming);
        cudaFuncSetAttribute(hgemm, cudaFuncAttributeMaxDynamicSharedMemorySize, GSMEM);
    }

#define SH(p, g) __half* p; cudaGetSymbolAddress((void**)&p, g)
#define SF(p, g) float* p; cudaGetSymbolAddress((void**)&p, g)
    SH(pXa, hX1a); SH(pMem, hMem); SH(pH1, hH1); SH(pC, hC);
    SH(pGh, hGh); SH(pGi, hGi);
    SH(pW1s, hW1s); SH(pW2T, hW2T); SH(pWih, hWih); SH(pWc, hWc);
    SH(pWhh, hWhh); SH(pWo, hWo);
    SF(pB1, dB1); SF(pBc, dBc); SF(pZero, dZero);
#undef SH
#undef SF

    #define CVT2(src, dst, n, st) conv_h<<<((n) / 2 + 255) / 256, 256, 0, st>>>(src, dst, n)

    // fork side stream
    cudaEventRecord(ev0, 0);
    cudaStreamWaitEvent(s2, ev0, 0);

    // side stream: weight prep chain + big memcpy
    CVT2(gru_w_hh, pWhh, 1536 * 512, s2);
    w2t_pack<<<(512 * 512 + 255) / 256, 256, 0, s2>>>(msg_w2);
    CVT2(gru_w_ih, pWih, 1536 * 512, s2);
    bc_pack<<<1536, 128, 0, s2>>>(gru_w_ih, msg_b2, gru_b_ih);
    hgemm<<<dim3(4, 12), 128, GSMEM, s2>>>(pWih, 512, pW2T, 512, 512, pZero,
                                           (float*)0, 0, pWc, 512, 2);
    CVT2(out_w, pWo, 512 * 1024, s2);
    emb_pack<<<Bn, 256, 0, s2>>>(src_emb, dst_emb);
    cudaEventRecord(evW, s2);
    cudaMemcpyAsync(out_mem, memory, (size_t)Nn * 512 * sizeof(float),
                    cudaMemcpyDeviceToDevice, s2);
    cudaEventRecord(evC, s2);

    // main stream: X1 path
    w1_pack<<<(1024 * K1 + 255) / 256, 256>>>(msg_w1);
    b1_pack<<<4, 256>>>(msg_b1);
    gather_pack<<<Bn, 256>>>(memory, edge, ts, time_w, time_b, src_ids, dst_ids);
    // layer1 fused: [H1a|H1b] <- X1a @ [W1;W1p]^T, relu, row-split output
    hgemm<<<dim3(8, Bn / 128), 128, GSMEM>>>(pXa, K1, pW1s, K1, K1, pB1,
                                             (float*)0, 0, pH1, 512, 3);
    cudaStreamWaitEvent(0, evW, 0);   // need Whh, Wc, bc, emb_pack, Wo
    // gh: [gh_s; gh_d] <- [src_mem; dst_mem] @ Whh^T (fp16 out)
    hgemm<<<dim3(12, 2 * Bn / 128), 128, GSMEM>>>(pMem, 512, pWhh, 512, 512,
                                                  gru_b_hh, (float*)0, 0, pGh, 1536, 2);
    // gi (msg2 fused): rows 0:Bn = H1a@Wc (gi_dst), Bn:2Bn = H1b@Wc (gi_src)
    hgemm<<<dim3(12, 2 * Bn / 128), 128, GSMEM>>>(pH1, 512, pWc, 512, 512,
                                                  pBc, (float*)0, 0, pGi, 1536, 2);
    cudaStreamWaitEvent(0, evC, 0);   // memcpy must complete before scatter
    gru_scatter<<<Bn, 128>>>(pGi + (size_t)Bn * 1536, pGh, memory, src_ids,
                             pC, out_mem);
    gru_scatter<<<Bn, 128>>>(pGi, pGh + (size_t)Bn * 1536, memory, dst_ids,
                             pC + (size_t)Bn * 1024, out_mem);
    // output projection: [2Bn,512] directly into d_out
    hgemm<<<dim3(4, 2 * Bn / 128), 128, GSMEM>>>(pC, 1024, pWo, 1024, 1024,
                                                 out_b, out_y, 512, (__half*)0, 0, 0);
}